// round 13
// baseline (speedup 1.0000x reference)
#include <cuda_runtime.h>
#include <cstdint>

// x: [8192,3] f32, y: [8192,3] f32, y_fea: [8192,16] f32 -> out [8192,16] f32
// k_sigma: exp(-200 d2)=e3^16, exp(-50 d2)=e3^4, exp(-12.5 d2)=e3; w=0.3/0.3/0.4
// Transposed GEMM, fp16 m16n8k16 (R12 pass1 verbatim, 42.7us).
// Scratch layout [kb][n][s][c]: 192B contiguous per (kb,n) -> float4 reduce.
// Reduce: thread = (n, c-quad, k-quarter), 512 blocks, 2-step shfl combine.

#define N_PTS    8192
#define M_PTS    8192
#define KB_SPLIT 16
#define M_PER_CTA (M_PTS / KB_SPLIT)     // 512
#define MS       256                     // m-tile staged in SMEM
#define NSTAGE   (M_PER_CTA / MS)        // 2
#define THREADS  256                     // 8 warps x 16 n = 128 n per CTA

typedef unsigned long long ull;

// static scratch (allocations are forbidden)
__device__ float g_U[KB_SPLIT][N_PTS][3][16];   // 25.2 MB, 192B per (kb,n)
__device__ float g_S[3][KB_SPLIT][N_PTS];       //  1.6 MB

__device__ __forceinline__ ull pack2(float a, float b) {
    ull r; asm("mov.b64 %0, {%1, %2};" : "=l"(r) : "f"(a), "f"(b)); return r;
}
__device__ __forceinline__ float2 unpack2(ull v) {
    float2 f; asm("mov.b64 {%0, %1}, %2;" : "=f"(f.x), "=f"(f.y) : "l"(v)); return f;
}
__device__ __forceinline__ ull add2(ull a, ull b) {
    ull r; asm("add.rn.f32x2 %0, %1, %2;" : "=l"(r) : "l"(a), "l"(b)); return r;
}
__device__ __forceinline__ ull mul2(ull a, ull b) {
    ull r; asm("mul.rn.f32x2 %0, %1, %2;" : "=l"(r) : "l"(a), "l"(b)); return r;
}
__device__ __forceinline__ ull fma2v(ull a, ull b, ull c) {
    ull r; asm("fma.rn.f32x2 %0, %1, %2, %3;" : "=l"(r) : "l"(a), "l"(b), "l"(c)); return r;
}
__device__ __forceinline__ float ex2f(float x) {
    float r; asm("ex2.approx.f32 %0, %1;" : "=f"(r) : "f"(x)); return r;
}
// d = { lo: cvt(lo), hi: cvt(hi) }  (first PTX source -> high half)
__device__ __forceinline__ uint32_t f16x2(float hi, float lo) {
    uint32_t d; asm("cvt.rn.f16x2.f32 %0, %1, %2;" : "=r"(d) : "f"(hi), "f"(lo));
    return d;
}
// packed f32x2 -> fp16x2 (x lane -> low half)
__device__ __forceinline__ uint32_t cvt2h(ull v) {
    const float2 f = unpack2(v);
    return f16x2(f.y, f.x);
}

// D (16c x 8n) += A (16x16 fp16, rows=c, k=m) * B (16x8 fp16, k=m, cols=n)
__device__ __forceinline__ void mma_f16(float* D, const uint4& A,
                                        uint32_t b0, uint32_t b1) {
    asm volatile(
        "mma.sync.aligned.m16n8k16.row.col.f32.f16.f16.f32 "
        "{%0,%1,%2,%3}, {%4,%5,%6,%7}, {%8,%9}, {%0,%1,%2,%3};"
        : "+f"(D[0]), "+f"(D[1]), "+f"(D[2]), "+f"(D[3])
        : "r"(A.x), "r"(A.y), "r"(A.z), "r"(A.w), "r"(b0), "r"(b1));
}

__global__ __launch_bounds__(THREADS, 3) void mgsc_pass1(
    const float* __restrict__ x,
    const float* __restrict__ y,
    const float* __restrict__ yfea)
{
    // ysw[pair]: consecutive (m=2p, m=2p+1) pairs; 4 u64 comps { y'0, y'1, y'2, b }
    // with y' = -2*Cexp*y, b = Cexp*|y|^2; lane x = even m, lane y = odd m.
    __shared__ __align__(16) ull ysw[MS / 2][4];              //  4 KB
    // yfrag[c16][lane][reg 0..3]: fp16x2 A-fragments in m16n8k16 order.
    // lane = g*4+t; reg r: c = g + 8*(r&1), ml = 2t + 8*(r>>1); pair (ml, ml+1).
    __shared__ __align__(16) uint32_t yfrag[(MS / 16) * 32 * 4];   // 8 KB

    const int tid  = threadIdx.x;
    const int warp = tid >> 5;
    const int lane = tid & 31;
    const int g    = lane >> 2;          // 0..7
    const int t    = lane & 3;           // 0..3
    const int nbA  = blockIdx.x * 128 + warp * 16;
    const int nbB  = nbA + 8;
    const int mstart = blockIdx.y * M_PER_CTA;
    const int kb   = blockIdx.y;

    const float Cexp = -12.5f * 1.44269504088896340736f;

    const int nA = nbA + g, nB = nbB + g;
    const float xa0 = x[nA*3+0], xa1 = x[nA*3+1], xa2 = x[nA*3+2];
    const float xb0 = x[nB*3+0], xb1 = x[nB*3+1], xb2 = x[nB*3+2];
    const float aa = Cexp * (xa0*xa0 + xa1*xa1 + xa2*xa2);
    const float ab = Cexp * (xb0*xb0 + xb1*xb1 + xb2*xb2);
    const ull XA0 = pack2(xa0, xa0), XA1 = pack2(xa1, xa1), XA2 = pack2(xa2, xa2);
    const ull XB0 = pack2(xb0, xb0), XB1 = pack2(xb1, xb1), XB2 = pack2(xb2, xb2);
    const ull APA = pack2(aa, aa),   APB = pack2(ab, ab);

    float DA[3][4], DB[3][4];
    ull SA[3] = {0,0,0}, SB[3] = {0,0,0};
    #pragma unroll
    for (int s = 0; s < 3; s++)
        #pragma unroll
        for (int q = 0; q < 4; q++) { DA[s][q] = 0.f; DB[s][q] = 0.f; }

    for (int st = 0; st < NSTAGE; st++) {
        if (st) __syncthreads();
        // ---- stage y: one consecutive (m, m+1) pair per thread (tid < 128) ----
        if (tid < MS / 2) {
            const int m0 = mstart + st * MS + 2 * tid;
            const float2 l0 = *reinterpret_cast<const float2*>(&y[m0*3]);
            const float2 l1 = *reinterpret_cast<const float2*>(&y[m0*3+2]);
            const float2 l2 = *reinterpret_cast<const float2*>(&y[m0*3+4]);
            const float e0 = l0.x, e1v = l0.y, e2v = l1.x;   // even m
            const float o0 = l1.y, o1v = l2.x, o2v = l2.y;   // odd m
            const float sc = -2.0f * Cexp;
            const float be = Cexp * (e0*e0 + e1v*e1v + e2v*e2v);
            const float bo = Cexp * (o0*o0 + o1v*o1v + o2v*o2v);
            ull* w = &ysw[tid][0];
            w[0] = pack2(sc * e0,  sc * o0);
            w[1] = pack2(sc * e1v, sc * o1v);
            w[2] = pack2(sc * e2v, sc * o2v);
            w[3] = pack2(be, bo);
        }
        // ---- stage y_fea as fp16 A-fragments: thread -> (blk, 2 lanes) ----
        {
            const int blk = tid >> 4;
            const int l0  = (tid & 15) * 2;
            const int mb  = mstart + st * MS + blk * 16;
            #pragma unroll
            for (int j = 0; j < 2; j++) {
                const int l  = l0 + j;
                const int gg = l >> 2, tt = l & 3;
                uint4 regs;
                uint32_t* rp = &regs.x;
                #pragma unroll
                for (int r = 0; r < 4; r++) {
                    const int c  = gg + 8 * (r & 1);
                    const int m  = mb + 2 * tt + 8 * (r >> 1);
                    rp[r] = f16x2(yfea[(m + 1) * 16 + c], yfea[m * 16 + c]);
                }
                *reinterpret_cast<uint4*>(&yfrag[(blk * 32 + l) * 4]) = regs;
            }
        }
        __syncthreads();

        #pragma unroll 4
        for (int c16 = 0; c16 < MS / 16; c16++) {
            const uint4 AF = *reinterpret_cast<const uint4*>(
                &yfrag[(c16 * 32 + lane) * 4]);                      // 1 LDS.128
            // chain 0: pair (2t, 2t+1); chain 1: pair (2t+8, 2t+9)
            const ulonglong2 p0a = *reinterpret_cast<const ulonglong2*>(&ysw[c16*8 + t][0]);
            const ulonglong2 p0b = *reinterpret_cast<const ulonglong2*>(&ysw[c16*8 + t][2]);
            const ulonglong2 p1a = *reinterpret_cast<const ulonglong2*>(&ysw[c16*8 + t + 4][0]);
            const ulonglong2 p1b = *reinterpret_cast<const ulonglong2*>(&ysw[c16*8 + t + 4][2]);

            // ================= group A =================
            {
                ull arg = add2(APA, p0b.y);
                arg = fma2v(XA0, p0a.x, arg);
                arg = fma2v(XA1, p0a.y, arg);
                arg = fma2v(XA2, p0b.x, arg);
                float2 f = unpack2(arg);
                const ull e3a = pack2(ex2f(f.x), ex2f(f.y));
                const ull qa  = mul2(e3a, e3a);
                const ull e2a = mul2(qa, qa);
                const ull ra  = mul2(e2a, e2a);
                const ull e1a = mul2(ra, ra);

                arg = add2(APA, p1b.y);
                arg = fma2v(XA0, p1a.x, arg);
                arg = fma2v(XA1, p1a.y, arg);
                arg = fma2v(XA2, p1b.x, arg);
                f = unpack2(arg);
                const ull e3b = pack2(ex2f(f.x), ex2f(f.y));
                const ull qb  = mul2(e3b, e3b);
                const ull e2b = mul2(qb, qb);
                const ull rb  = mul2(e2b, e2b);
                const ull e1b = mul2(rb, rb);

                SA[0] = add2(SA[0], add2(e1a, e1b));
                SA[1] = add2(SA[1], add2(e2a, e2b));
                SA[2] = add2(SA[2], add2(e3a, e3b));

                mma_f16(DA[0], AF, cvt2h(e1a), cvt2h(e1b));
                mma_f16(DA[1], AF, cvt2h(e2a), cvt2h(e2b));
                mma_f16(DA[2], AF, cvt2h(e3a), cvt2h(e3b));
            }
            // ================= group B =================
            {
                ull arg = add2(APB, p0b.y);
                arg = fma2v(XB0, p0a.x, arg);
                arg = fma2v(XB1, p0a.y, arg);
                arg = fma2v(XB2, p0b.x, arg);
                float2 f = unpack2(arg);
                const ull e3a = pack2(ex2f(f.x), ex2f(f.y));
                const ull qa  = mul2(e3a, e3a);
                const ull e2a = mul2(qa, qa);
                const ull ra  = mul2(e2a, e2a);
                const ull e1a = mul2(ra, ra);

                arg = add2(APB, p1b.y);
                arg = fma2v(XB0, p1a.x, arg);
                arg = fma2v(XB1, p1a.y, arg);
                arg = fma2v(XB2, p1b.x, arg);
                f = unpack2(arg);
                const ull e3b = pack2(ex2f(f.x), ex2f(f.y));
                const ull qb  = mul2(e3b, e3b);
                const ull e2b = mul2(qb, qb);
                const ull rb  = mul2(e2b, e2b);
                const ull e1b = mul2(rb, rb);

                SB[0] = add2(SB[0], add2(e1a, e1b));
                SB[1] = add2(SB[1], add2(e2a, e2b));
                SB[2] = add2(SB[2], add2(e3a, e3b));

                mma_f16(DB[0], AF, cvt2h(e1a), cvt2h(e1b));
                mma_f16(DB[1], AF, cvt2h(e2a), cvt2h(e2b));
                mma_f16(DB[2], AF, cvt2h(e3a), cvt2h(e3b));
            }
        }
    }

    // ---- row-sums: horizontal add + reduce over the 4 t-lanes of each n ----
    #pragma unroll
    for (int s = 0; s < 3; s++) {
        float2 v = unpack2(SA[s]);
        float rs = v.x + v.y;
        rs += __shfl_xor_sync(0xffffffffu, rs, 1);
        rs += __shfl_xor_sync(0xffffffffu, rs, 2);
        if (t == 0) g_S[s][kb][nA] = rs;
        v = unpack2(SB[s]);
        float rb = v.x + v.y;
        rb += __shfl_xor_sync(0xffffffffu, rb, 1);
        rb += __shfl_xor_sync(0xffffffffu, rb, 2);
        if (t == 0) g_S[s][kb][nB] = rb;
    }
    // ---- D -> g_U (layout [kb][n][s][c]) ----
    {
        const int a0 = nbA + 2*t, a1 = a0 + 1;
        const int b0 = nbB + 2*t, b1 = b0 + 1;
        #pragma unroll
        for (int s = 0; s < 3; s++) {
            g_U[kb][a0][s][g]     = DA[s][0];
            g_U[kb][a1][s][g]     = DA[s][1];
            g_U[kb][a0][s][g + 8] = DA[s][2];
            g_U[kb][a1][s][g + 8] = DA[s][3];
            g_U[kb][b0][s][g]     = DB[s][0];
            g_U[kb][b1][s][g]     = DB[s][1];
            g_U[kb][b0][s][g + 8] = DB[s][2];
            g_U[kb][b1][s][g + 8] = DB[s][3];
        }
    }
}

__global__ __launch_bounds__(256) void mgsc_reduce(float* __restrict__ out)
{
    // thread = (n, c-quad, k-quarter): 131072 threads -> 512 blocks.
    // Per thread: 12 float4 U-loads + 12 scalar S-loads, all independent.
    const int idx     = blockIdx.x * 256 + threadIdx.x;
    const int c4      = idx & 3;           // c-quad (4 floats)
    const int quarter = (idx >> 2) & 3;    // k-quarter
    const int n       = idx >> 4;
    const int k0      = quarter * (KB_SPLIT / 4);

    float4 u[3];
    float  sm[3];
    #pragma unroll
    for (int s = 0; s < 3; s++) { u[s] = make_float4(0,0,0,0); sm[s] = 0.f; }

    #pragma unroll
    for (int k = 0; k < KB_SPLIT / 4; k++) {
        #pragma unroll
        for (int s = 0; s < 3; s++) {
            const float4 v = *reinterpret_cast<const float4*>(&g_U[k0 + k][n][s][c4 * 4]);
            u[s].x += v.x; u[s].y += v.y; u[s].z += v.z; u[s].w += v.w;
            sm[s] += g_S[s][k0 + k][n];
        }
    }

    const float w[3] = {0.3f, 0.3f, 0.4f};
    float4 acc = make_float4(0,0,0,0);
    #pragma unroll
    for (int s = 0; s < 3; s++) {
        float4 uu = u[s];
        float  ss = sm[s];
        uu.x += __shfl_xor_sync(0xffffffffu, uu.x, 4);
        uu.y += __shfl_xor_sync(0xffffffffu, uu.y, 4);
        uu.z += __shfl_xor_sync(0xffffffffu, uu.z, 4);
        uu.w += __shfl_xor_sync(0xffffffffu, uu.w, 4);
        ss   += __shfl_xor_sync(0xffffffffu, ss,   4);
        uu.x += __shfl_xor_sync(0xffffffffu, uu.x, 8);
        uu.y += __shfl_xor_sync(0xffffffffu, uu.y, 8);
        uu.z += __shfl_xor_sync(0xffffffffu, uu.z, 8);
        uu.w += __shfl_xor_sync(0xffffffffu, uu.w, 8);
        ss   += __shfl_xor_sync(0xffffffffu, ss,   8);
        const float iv = w[s] / ss;
        acc.x += uu.x * iv; acc.y += uu.y * iv;
        acc.z += uu.z * iv; acc.w += uu.w * iv;
    }
    if (quarter == 0)
        *reinterpret_cast<float4*>(&out[n * 16 + c4 * 4]) = acc;
}

extern "C" void kernel_launch(void* const* d_in, const int* in_sizes, int n_in,
                              void* d_out, int out_size)
{
    const float* x    = (const float*)d_in[0];
    const float* y    = (const float*)d_in[1];
    const float* yfea = (const float*)d_in[2];
    float*       out  = (float*)d_out;

    dim3 grid(N_PTS / 128, KB_SPLIT);        // (64, 16) = 1024 CTAs
    mgsc_pass1<<<grid, THREADS>>>(x, y, yfea);
    mgsc_reduce<<<(N_PTS * 16) / 256, 256>>>(out);   // 512 blocks
}